// round 14
// baseline (speedup 1.0000x reference)
#include <cuda_runtime.h>
#include <math.h>

#define BB 128
#define SS 256
#define NLAB 9
#define SMALLV (-1000.0f)

// ---------------- f32x2 packed-FMA + fast-tanh helpers (sm_100+) ----------------
typedef unsigned long long u64;

__device__ __forceinline__ u64 pk2(float lo, float hi){
    u64 r; asm("mov.b64 %0, {%1, %2};" : "=l"(r) : "f"(lo), "f"(hi)); return r;
}
__device__ __forceinline__ void upk2(float& lo, float& hi, u64 v){
    asm("mov.b64 {%0, %1}, %2;" : "=f"(lo), "=f"(hi) : "l"(v));
}
__device__ __forceinline__ u64 fma2(u64 a, u64 b, u64 c){
    u64 d; asm("fma.rn.f32x2 %0, %1, %2, %3;" : "=l"(d) : "l"(a), "l"(b), "l"(c)); return d;
}
__device__ __forceinline__ float tanhfast(float x){
    float y; asm("tanh.approx.f32 %0, %1;" : "=f"(y) : "f"(x)); return y;
}
__device__ __forceinline__ float sigfast(float x){
    return fmaf(tanhfast(0.5f*x), 0.5f, 0.5f);
}

// ---------------- scratch (__device__ globals, no allocation) ----------------
__device__ float  d_Ef[100*100];          // char_emb @ cWih_f^T + cb_f  [row][gate]
__device__ float  d_Eb[100*100];
__device__ float2 d_cWhhP_f[12*100];      // char Whh packed k-pairs [kp][gate_row]
__device__ float2 d_cWhhP_b[12*100];
__device__ float  d_cW24_f[100];          // char Whh k=24 column
__device__ float  d_cW24_b[100];
__device__ float2 d_WihP_f[75*400];       // word Wih packed k-pairs [kp][gate]
__device__ float2 d_WihP_b[75*400];
__device__ float2 d_wWhhP_f[50*400];      // word Whh packed k-pairs [kp][gate]
__device__ float2 d_wWhhP_b[50*400];
__device__ float2 d_W1P[100*100];         // W1 packed k-pairs [kp][g]
__device__ float  g_char_out[BB*SS*50];
// gpre pair-interleaved: u64 index (b*128 + t/2)*400 + g holds {t even, t odd}
// NOTE: forward gpre at fully-masked 32-row tiles is never written (stays 0);
// those values only influence masked outputs, which are never consumed.
__device__ float  g_gpre_f[(size_t)BB*SS*400];
__device__ float  g_gpre_b[(size_t)BB*SS*400];
__device__ float  g_wh[(size_t)BB*SS*200];
__device__ float  g_feats[BB*SS*NLAB];
__device__ float  g_perb[BB];

// ---------------- K0a: prep needed by char_lstm (E tables + char Whh) ---------
__global__ void prep_char_kernel(const float* __restrict__ char_emb,
                                 const float* __restrict__ cWih_f, const float* __restrict__ cb_f,
                                 const float* __restrict__ cWih_b, const float* __restrict__ cb_b,
                                 const float* __restrict__ cWhh_f, const float* __restrict__ cWhh_b)
{
    int tid = blockIdx.x*blockDim.x + threadIdx.x;
    if (tid < 20000) {                              // E tables
        int which = tid / 10000;
        int r = (tid % 10000) / 100;
        int g = tid % 100;
        const float* W  = which ? cWih_b : cWih_f;
        const float* bb = which ? cb_b   : cb_f;
        float acc = bb[g];
        #pragma unroll
        for (int k = 0; k < 25; k++) acc += char_emb[r*25+k] * W[g*25+k];
        (which ? d_Eb : d_Ef)[r*100+g] = acc;
        return;
    }
    int t3 = tid - 20000;
    if (t3 < 2400) {                                // char Whh packed: 2 x 12 x 100
        int which = t3 / 1200;
        int rem = t3 % 1200;
        int kp = rem / 100, g = rem % 100;
        const float* W = which ? cWhh_b : cWhh_f;
        (which ? d_cWhhP_b : d_cWhhP_f)[kp*100+g] = make_float2(W[g*25+2*kp], W[g*25+2*kp+1]);
        return;
    }
    int t4 = t3 - 2400;
    if (t4 < 200) {                                 // char Whh k=24 column
        int which = t4 / 100;
        int g = t4 % 100;
        const float* W = which ? cWhh_b : cWhh_f;
        (which ? d_cW24_b : d_cW24_f)[g] = W[g*25+24];
    }
}

// ---------------- K0b: prep for word stages (runs concurrently w/ char_lstm) --
__global__ void prep_word_kernel(const float* __restrict__ wWih_f, const float* __restrict__ wWih_b,
                                 const float* __restrict__ wWhh_f, const float* __restrict__ wWhh_b,
                                 const float* __restrict__ W1)
{
    int tid = blockIdx.x*blockDim.x + threadIdx.x;
    if (tid < 60000) {                              // word Wih packed: 2 x 75 x 400
        int which = tid / 30000;
        int rem = tid % 30000;
        int kp = rem / 400, g = rem % 400;
        const float* W = which ? wWih_b : wWih_f;
        (which ? d_WihP_b : d_WihP_f)[kp*400+g] = make_float2(W[g*150+2*kp], W[g*150+2*kp+1]);
        return;
    }
    int t2 = tid - 60000;
    if (t2 < 10000) {                               // W1 packed: 100 x 100
        int kp = t2 / 100, g = t2 % 100;
        d_W1P[kp*100+g] = make_float2(W1[g*200+2*kp], W1[g*200+2*kp+1]);
        return;
    }
    int t5 = t2 - 10000;
    if (t5 < 40000) {                               // word Whh packed: 2 x 50 x 400
        int which = t5 / 20000;
        int rem = t5 % 20000;
        int kp = rem / 400, g = rem % 400;
        const float* W = which ? wWhh_b : wWhh_f;
        (which ? d_wWhhP_b : d_wWhhP_f)[kp*400+g] = make_float2(W[g*100+2*kp], W[g*100+2*kp+1]);
    }
}

// ---------------- K1: char BiLSTM, one warp per (sequence, direction) ---------
__global__ void __launch_bounds__(256,2) char_lstm_kernel(
    const int* __restrict__ char_ids, const int* __restrict__ word_num)
{
    int warp = threadIdx.x >> 5;
    int lane = threadIdx.x & 31;
    int task = blockIdx.x*8 + warp;          // < 65536
    int seq = task >> 1;
    int dir = task & 1;

    // early-exit for masked sequences: char_out must be zero
    if ((seq & 255) >= word_num[seq >> 8]) {
        if (lane < 25) g_char_out[seq*50 + dir*25 + lane] = 0.f;
        return;
    }

    const float2* WhhP = dir ? d_cWhhP_b : d_cWhhP_f;
    const float*  W24  = dir ? d_cW24_b  : d_cW24_f;
    const float*  Etab = dir ? d_Eb : d_Ef;
    int l = (lane < 25) ? lane : 0;

    u64 wp[4][12]; float w24[4];
    #pragma unroll
    for (int j = 0; j < 4; j++) {
        #pragma unroll
        for (int kp = 0; kp < 12; kp++)
            wp[j][kp] = *(const u64*)&WhhP[kp*100 + 25*j + l];
        w24[j] = __ldg(&W24[25*j + l]);
    }

    __shared__ __align__(16) float sh[8][32];
    sh[warp][lane] = 0.f;
    __syncwarp();

    int idreg = (lane < 16) ? char_ids[seq*16 + lane] : 0;
    float c = 0.f, h = 0.f;

    #pragma unroll 1
    for (int t = 0; t < 16; t++) {
        int ct = dir ? (15 - t) : t;
        int row = __shfl_sync(0xffffffffu, idreg, ct);
        const float* e = Etab + row*100;
        u64 acc[4];
        acc[0] = pk2(__ldg(&e[l]),    0.f);
        acc[1] = pk2(__ldg(&e[25+l]), 0.f);
        acc[2] = pk2(__ldg(&e[50+l]), 0.f);
        acc[3] = pk2(__ldg(&e[75+l]), 0.f);
        const ulonglong2* h2 = (const ulonglong2*)sh[warp];
        #pragma unroll
        for (int k4 = 0; k4 < 6; k4++) {
            ulonglong2 v = h2[k4];
            #pragma unroll
            for (int j = 0; j < 4; j++) {
                acc[j] = fma2(wp[j][2*k4],   v.x, acc[j]);
                acc[j] = fma2(wp[j][2*k4+1], v.y, acc[j]);
            }
        }
        float h24 = sh[warp][24];
        float a[4];
        #pragma unroll
        for (int j = 0; j < 4; j++) {
            float lo, hi; upk2(lo, hi, acc[j]);
            a[j] = lo + hi + w24[j]*h24;
        }
        __syncwarp();
        float i_ = sigfast(a[0]);
        float f_ = sigfast(a[1]);
        float gg = tanhfast(a[2]);
        float o_ = sigfast(a[3]);
        c = f_*c + i_*gg;
        h = o_*tanhfast(c);
        if (lane < 25) sh[warp][lane] = h;
        __syncwarp();
    }
    if (lane < 25) {
        g_char_out[seq*50 + dir*25 + lane] = h;   // unmasked path: mask = 1
    }
}

// ---------------- K2: word input projection (coarsened, masked-fwd skip) ------
// 32 rows x 100 gates x 1 dir per block, 128 threads; thread = 4 gates x 8 rows.
// Forward-dir blocks on fully-masked tiles exit (gpre_f stays 0 there; those
// values only influence masked outputs).
__global__ void __launch_bounds__(128) word_proj_kernel(
    const float* __restrict__ word_emb, const int* __restrict__ word_ids,
    const float* __restrict__ wb_f, const float* __restrict__ wb_b,
    const int* __restrict__ word_num)
{
    int rowbase = blockIdx.x * 32;
    int gbase = blockIdx.y * 100;
    int dir = blockIdx.z;
    if (dir == 0 && (rowbase & 255) >= word_num[rowbase >> 8]) return;

    int tx = threadIdx.x & 31;
    int ty = threadIdx.x >> 5;   // 0..3

    __shared__ __align__(16) float sA[32*152];
    __shared__ int swid[32];

    if (threadIdx.x < 32) swid[threadIdx.x] = word_ids[rowbase + threadIdx.x];
    __syncthreads();
    for (int idx = threadIdx.x; idx < 32*150; idx += 128) {
        int r = idx / 150, k = idx % 150;
        float v;
        if (k < 100) v = __ldg(&word_emb[(size_t)swid[r]*100 + k]);
        else         v = g_char_out[(rowbase + r)*50 + (k - 100)];
        sA[r*152 + k] = v;
    }
    __syncthreads();

    const float2* WP  = dir ? d_WihP_b : d_WihP_f;
    const float* bias = dir ? wb_b : wb_f;
    int gidx[4]; bool gok[4];
    u64 acc[4][8];
    u64 z = pk2(0.f, 0.f);
    #pragma unroll
    for (int i = 0; i < 4; i++) {
        int lg = tx + 32*i;
        gok[i] = (lg < 100);
        gidx[i] = gbase + (gok[i] ? lg : 0);
        #pragma unroll
        for (int j = 0; j < 8; j++) acc[i][j] = z;
    }
    #pragma unroll 2
    for (int kp = 0; kp < 75; kp++) {
        u64 w[4];
        #pragma unroll
        for (int i = 0; i < 4; i++) w[i] = *(const u64*)&WP[kp*400 + gidx[i]];
        u64 a[8];
        #pragma unroll
        for (int j = 0; j < 8; j++) a[j] = *(const u64*)&sA[(ty + 4*j)*152 + 2*kp];
        #pragma unroll
        for (int i = 0; i < 4; i++) {
            #pragma unroll
            for (int j = 0; j < 8; j++) acc[i][j] = fma2(w[i], a[j], acc[i][j]);
        }
    }
    float* out = dir ? g_gpre_b : g_gpre_f;
    #pragma unroll
    for (int i = 0; i < 4; i++) {
        if (!gok[i]) continue;
        float bv = __ldg(&bias[gidx[i]]);
        #pragma unroll
        for (int j = 0; j < 8; j++) {
            size_t row = (size_t)(rowbase + ty + 4*j);
            float lo, hi;
            upk2(lo, hi, acc[i][j]);
            // pair-interleaved: ((row/2)*400 + g)*2 + (row&1)
            out[((row >> 1)*400 + gidx[i])*2 + (row & 1)] = bv + lo + hi;
        }
    }
}

// ---------------- K3: word BiLSTM recurrence (pair-interleaved gpre loads) ----
__global__ void __launch_bounds__(400,1) word_rec_kernel()
{
    int dir  = blockIdx.x & 1;
    int pair = blockIdx.x >> 1;
    int b0 = pair*2, b1 = b0 + 1;
    int g = threadIdx.x;                 // 0..399, all workers
    const float2* WhhP = dir ? d_wWhhP_b : d_wWhhP_f;

    u64 wp[50];
    #pragma unroll
    for (int kp = 0; kp < 50; kp++)
        wp[kp] = *(const u64*)&WhhP[kp*400 + g];

    __shared__ __align__(16) float sh0[100], sh1[100];
    __shared__ float sg0[400], sg1[400];
    if (g < 100) { sh0[g] = 0.f; sh1[g] = 0.f; }
    float c = 0.f;
    __syncthreads();

    const u64* gp0 = ((const u64*)(dir ? g_gpre_b : g_gpre_f)) + (size_t)b0*128*400;
    const u64* gp1 = ((const u64*)(dir ? g_gpre_b : g_gpre_f)) + (size_t)b1*128*400;

    int pfirst = dir ? 127 : 0;
    u64 pf0 = gp0[pfirst*400 + g];
    u64 pf1 = gp1[pfirst*400 + g];
    // branch-free nonlinearity: y = na*tanhfast(ns*x) + nb
    bool isg = (g >= 200 && g < 300);
    float ns = isg ? 1.0f : 0.5f;
    float na = ns;
    float nb = isg ? 0.0f : 0.5f;

    #pragma unroll 1
    for (int pp = 0; pp < 128; pp++) {
        int p = dir ? (127 - pp) : pp;
        u64 cp0 = pf0, cp1 = pf1;
        if (pp < 127) {
            int pn = dir ? (126 - pp) : (pp + 1);
            pf0 = gp0[pn*400 + g];
            pf1 = gp1[pn*400 + g];
        }
        float ev0, od0, ev1, od1;
        upk2(ev0, od0, cp0);
        upk2(ev1, od1, cp1);
        #pragma unroll
        for (int sub = 0; sub < 2; sub++) {
            int ts = 2*p + (dir ? (1 - sub) : sub);
            float cur0 = (ts & 1) ? od0 : ev0;
            float cur1 = (ts & 1) ? od1 : ev1;
            {
                u64 a0x = pk2(cur0, 0.f), a0y = pk2(0.f, 0.f);
                u64 a1x = pk2(cur1, 0.f), a1y = pk2(0.f, 0.f);
                const ulonglong2* h20 = (const ulonglong2*)sh0;
                const ulonglong2* h21 = (const ulonglong2*)sh1;
                #pragma unroll
                for (int k4 = 0; k4 < 25; k4++) {
                    ulonglong2 v0 = h20[k4];
                    ulonglong2 v1 = h21[k4];
                    a0x = fma2(wp[2*k4],   v0.x, a0x);
                    a0y = fma2(wp[2*k4+1], v0.y, a0y);
                    a1x = fma2(wp[2*k4],   v1.x, a1x);
                    a1y = fma2(wp[2*k4+1], v1.y, a1y);
                }
                float l0,h0v,l1,h1v,l2,h2v,l3,h3v;
                upk2(l0,h0v,a0x); upk2(l1,h1v,a0y);
                upk2(l2,h2v,a1x); upk2(l3,h3v,a1y);
                float x0 = (l0+h0v) + (l1+h1v);
                float x1 = (l2+h2v) + (l3+h3v);
                sg0[g] = fmaf(na, tanhfast(ns*x0), nb);
                sg1[g] = fmaf(na, tanhfast(ns*x1), nb);
            }
            __syncthreads();
            if (g < 200) {
                int s = (g >= 100); int j = g - s*100;
                const float* sg = s ? sg1 : sg0;
                float i_ = sg[j];
                float f_ = sg[100+j];
                float gt = sg[200+j];
                float o_ = sg[300+j];
                c = f_*c + i_*gt;
                float h = o_*tanhfast(c);
                (s ? sh1 : sh0)[j] = h;
                g_wh[((size_t)((b0+s)*256 + ts))*200 + dir*100 + j] = h;
            }
            __syncthreads();
        }
    }
}

// ---------------- K4: MLP (pair-packed W1, masked-group early exit) -----------
__global__ void __launch_bounds__(128) mlp_kernel(
    const float* __restrict__ b1, const float* __restrict__ W2,
    const float* __restrict__ b2, const int* __restrict__ word_num)
{
    int rowbase = blockIdx.x * 16;
    int wn = word_num[rowbase >> 8];
    if ((rowbase & 255) >= wn) return;   // whole 16-row group masked -> unused

    __shared__ __align__(16) float sX[16*200];
    __shared__ float sH[16*104];
    int tid = threadIdx.x;

    for (int idx = tid; idx < 3200; idx += 128)
        sX[idx] = g_wh[(size_t)rowbase*200 + idx];
    __syncthreads();
    if (tid < 100) {
        u64 a2[16];
        u64 z = pk2(0.f, 0.f);
        #pragma unroll
        for (int r = 0; r < 16; r++) a2[r] = z;
        #pragma unroll 2
        for (int kp = 0; kp < 100; kp++) {
            u64 wv = *(const u64*)&d_W1P[kp*100 + tid];
            #pragma unroll
            for (int r = 0; r < 16; r++)
                a2[r] = fma2(wv, *(const u64*)&sX[r*200 + 2*kp], a2[r]);
        }
        float bv = __ldg(&b1[tid]);
        #pragma unroll
        for (int r = 0; r < 16; r++) {
            float lo, hi; upk2(lo, hi, a2[r]);
            sH[r*104 + tid] = tanhfast(bv + lo + hi);
        }
    }
    __syncthreads();
    #pragma unroll
    for (int pass = 0; pass < 2; pass++) {
        int idx = tid + pass*128;
        if (idx < 144) {
            int r = idx / 9, o = idx % 9;
            int row = rowbase + r;
            float acc = __ldg(&b2[o]);
            #pragma unroll 4
            for (int k = 0; k < 100; k++)
                acc += __ldg(&W2[o*100 + k]) * sH[r*104 + k];
            float m = ((row & 255) < wn) ? 1.0f : 0.0f;
            g_feats[row*9 + o] = acc * m;
        }
    }
}

// ---------------- K5: CRF (parallel numerator + forward algorithm) ------------
__global__ void crf_kernel(const float* __restrict__ transition,
                           const int* __restrict__ word_num,
                           const int* __restrict__ label_ids)
{
    int b = blockIdx.x;
    int lane = threadIdx.x;
    __shared__ float sT[121];
    __shared__ int sLab[256];
    for (int i = lane; i < 121; i += 32) sT[i] = transition[i];
    #pragma unroll
    for (int r = 0; r < 8; r++) sLab[lane + 32*r] = label_ids[b*256 + lane + 32*r];
    __syncwarp();
    int wn = word_num[b];

    // --- numerator: lane-parallel gold-path score ---
    float part = 0.f;
    #pragma unroll
    for (int r = 0; r < 8; r++) {
        int t = lane + 32*r;
        if (t < wn) {
            int lab = sLab[t];
            int prv = (t == 0) ? 9 : sLab[t-1];
            part += g_feats[(size_t)(b*256 + t)*9 + lab] + sT[prv*11 + lab];
        }
    }
    #pragma unroll
    for (int off = 16; off > 0; off >>= 1)
        part += __shfl_xor_sync(0xffffffffu, part, off);
    float num = part + sT[sLab[wn-1]*11 + 10];

    // --- denominator: forward algorithm ---
    float alpha = (lane == 9) ? 0.0f : SMALLV;   // start state = 9
    int jj = (lane < 11) ? lane : 0;
    for (int t = 0; t < wn; t++) {
        float obs = (lane < 9) ? g_feats[(size_t)(b*256 + t)*9 + lane] : SMALLV;
        float av[11];
        #pragma unroll
        for (int k = 0; k < 11; k++) av[k] = __shfl_sync(0xffffffffu, alpha, k);
        float mx = -3.0e38f;
        float vv[11];
        #pragma unroll
        for (int k = 0; k < 11; k++) { vv[k] = av[k] + sT[k*11 + jj]; mx = fmaxf(mx, vv[k]); }
        float s = 0.f;
        #pragma unroll
        for (int k = 0; k < 11; k++) s += expf(vv[k] - mx);
        float anew = obs + mx + logf(s);
        alpha = (lane < 11) ? anew : SMALLV;
    }
    float av[11];
    #pragma unroll
    for (int k = 0; k < 11; k++) av[k] = __shfl_sync(0xffffffffu, alpha, k);
    if (lane == 0) {
        float mx = -3.0e38f; float vv[11];
        #pragma unroll
        for (int k = 0; k < 11; k++) { vv[k] = av[k] + sT[k*11 + 10]; mx = fmaxf(mx, vv[k]); }
        float s = 0.f;
        #pragma unroll
        for (int k = 0; k < 11; k++) s += expf(vv[k] - mx);
        float denom = mx + logf(s);
        g_perb[b] = denom - num;
    }
}

// ---------------- K6: deterministic mean reduction ----------------------------
__global__ void finalize_kernel(float* out)
{
    __shared__ float s[128];
    int tid = threadIdx.x;
    s[tid] = g_perb[tid];
    __syncthreads();
    for (int off = 64; off > 0; off >>= 1) {
        if (tid < off) s[tid] += s[tid + off];
        __syncthreads();
    }
    if (tid == 0) out[0] = s[0] * (1.0f/128.0f);
}

// ---------------- launch -------------------------------------------------------
extern "C" void kernel_launch(void* const* d_in, const int* in_sizes, int n_in,
                              void* d_out, int out_size)
{
    (void)in_sizes; (void)n_in; (void)out_size;
    const float* word_emb   = (const float*)d_in[0];
    const float* char_emb   = (const float*)d_in[1];
    const float* cWih_f     = (const float*)d_in[2];
    const float* cWhh_f     = (const float*)d_in[3];
    const float* cb_f       = (const float*)d_in[4];
    const float* cWih_b     = (const float*)d_in[5];
    const float* cWhh_b     = (const float*)d_in[6];
    const float* cb_b       = (const float*)d_in[7];
    const float* wWih_f     = (const float*)d_in[8];
    const float* wWhh_f     = (const float*)d_in[9];
    const float* wb_f       = (const float*)d_in[10];
    const float* wWih_b     = (const float*)d_in[11];
    const float* wWhh_b     = (const float*)d_in[12];
    const float* wb_b       = (const float*)d_in[13];
    const float* W1         = (const float*)d_in[14];
    const float* b1         = (const float*)d_in[15];
    const float* W2         = (const float*)d_in[16];
    const float* b2         = (const float*)d_in[17];
    const float* transition = (const float*)d_in[18];
    const int*   word_num   = (const int*)d_in[19];
    const int*   word_ids   = (const int*)d_in[20];
    const int*   char_ids   = (const int*)d_in[21];
    const int*   label_ids  = (const int*)d_in[22];

    static cudaStream_t s2 = 0;
    static cudaEvent_t evFork = 0, evJoin = 0;
    if (s2 == 0) {
        cudaStreamCreateWithFlags(&s2, cudaStreamNonBlocking);
        cudaEventCreateWithFlags(&evFork, cudaEventDisableTiming);
        cudaEventCreateWithFlags(&evJoin, cudaEventDisableTiming);
    }

    prep_char_kernel<<<89, 256>>>(char_emb, cWih_f, cb_f, cWih_b, cb_b, cWhh_f, cWhh_b);

    // prep_word runs concurrently with char_lstm (no data dependence)
    cudaEventRecord(evFork, 0);
    cudaStreamWaitEvent(s2, evFork, 0);
    prep_word_kernel<<<430, 256, 0, s2>>>(wWih_f, wWih_b, wWhh_f, wWhh_b, W1);

    char_lstm_kernel<<<8192, 256>>>(char_ids, word_num);

    // join: word_proj needs both char_out (stream 0) and packed Wih (s2)
    cudaEventRecord(evJoin, s2);
    cudaStreamWaitEvent(0, evJoin, 0);

    dim3 g2(1024, 4, 2);
    word_proj_kernel<<<g2, 128>>>(word_emb, word_ids, wb_f, wb_b, word_num);
    word_rec_kernel<<<128, 400>>>();
    mlp_kernel<<<2048, 128>>>(b1, W2, b2, word_num);
    crf_kernel<<<128, 32>>>(transition, word_num, label_ids);
    finalize_kernel<<<1, 128>>>((float*)d_out);
}

// round 15
// speedup vs baseline: 1.8063x; 1.8063x over previous
#include <cuda_runtime.h>
#include <math.h>

#define BB 128
#define SS 256
#define NLAB 9
#define SMALLV (-1000.0f)

// ---------------- f32x2 packed-FMA + fast-tanh helpers (sm_100+) ----------------
typedef unsigned long long u64;

__device__ __forceinline__ u64 pk2(float lo, float hi){
    u64 r; asm("mov.b64 %0, {%1, %2};" : "=l"(r) : "f"(lo), "f"(hi)); return r;
}
__device__ __forceinline__ void upk2(float& lo, float& hi, u64 v){
    asm("mov.b64 {%0, %1}, %2;" : "=f"(lo), "=f"(hi) : "l"(v));
}
__device__ __forceinline__ u64 fma2(u64 a, u64 b, u64 c){
    u64 d; asm("fma.rn.f32x2 %0, %1, %2, %3;" : "=l"(d) : "l"(a), "l"(b), "l"(c)); return d;
}
__device__ __forceinline__ float tanhfast(float x){
    float y; asm("tanh.approx.f32 %0, %1;" : "=f"(y) : "f"(x)); return y;
}
__device__ __forceinline__ float sigfast(float x){
    return fmaf(tanhfast(0.5f*x), 0.5f, 0.5f);
}

// ---------------- scratch (__device__ globals, no allocation) ----------------
__device__ float  d_Ef[100*100];          // char_emb @ cWih_f^T + cb_f  [row][gate]
__device__ float  d_Eb[100*100];
__device__ float2 d_cWhhP_f[12*100];      // char Whh packed k-pairs [kp][gate_row]
__device__ float2 d_cWhhP_b[12*100];
__device__ float  d_cW24_f[100];          // char Whh k=24 column
__device__ float  d_cW24_b[100];
__device__ float2 d_WihP_f[75*400];       // word Wih packed k-pairs [kp][gate]
__device__ float2 d_WihP_b[75*400];
__device__ float2 d_wWhhP_f[50*400];      // word Whh packed k-pairs [kp][gate]
__device__ float2 d_wWhhP_b[50*400];
__device__ float2 d_W1P[100*100];         // W1 packed k-pairs [kp][g]
__device__ float  g_char_out[BB*SS*50];
// gpre pair-interleaved: u64 index (b*128 + t/2)*400 + g holds {t even, t odd}
// NOTE: forward gpre at fully-masked 32-row tiles is never written (stays 0);
// those values only influence masked outputs, which are never consumed.
__device__ float  g_gpre_f[(size_t)BB*SS*400];
__device__ float  g_gpre_b[(size_t)BB*SS*400];
__device__ float  g_wh[(size_t)BB*SS*200];
__device__ float  g_feats[BB*SS*NLAB];
__device__ float  g_perb[BB];

// ---------------- K0a: prep needed by char_lstm (E tables + char Whh) ---------
__global__ void prep_char_kernel(const float* __restrict__ char_emb,
                                 const float* __restrict__ cWih_f, const float* __restrict__ cb_f,
                                 const float* __restrict__ cWih_b, const float* __restrict__ cb_b,
                                 const float* __restrict__ cWhh_f, const float* __restrict__ cWhh_b)
{
    int tid = blockIdx.x*blockDim.x + threadIdx.x;
    if (tid < 20000) {                              // E tables
        int which = tid / 10000;
        int r = (tid % 10000) / 100;
        int g = tid % 100;
        const float* W  = which ? cWih_b : cWih_f;
        const float* bb = which ? cb_b   : cb_f;
        float acc = bb[g];
        #pragma unroll
        for (int k = 0; k < 25; k++) acc += char_emb[r*25+k] * W[g*25+k];
        (which ? d_Eb : d_Ef)[r*100+g] = acc;
        return;
    }
    int t3 = tid - 20000;
    if (t3 < 2400) {                                // char Whh packed: 2 x 12 x 100
        int which = t3 / 1200;
        int rem = t3 % 1200;
        int kp = rem / 100, g = rem % 100;
        const float* W = which ? cWhh_b : cWhh_f;
        (which ? d_cWhhP_b : d_cWhhP_f)[kp*100+g] = make_float2(W[g*25+2*kp], W[g*25+2*kp+1]);
        return;
    }
    int t4 = t3 - 2400;
    if (t4 < 200) {                                 // char Whh k=24 column
        int which = t4 / 100;
        int g = t4 % 100;
        const float* W = which ? cWhh_b : cWhh_f;
        (which ? d_cW24_b : d_cW24_f)[g] = W[g*25+24];
    }
}

// ---------------- K0b: prep for word stages (runs concurrently w/ char_lstm) --
__global__ void prep_word_kernel(const float* __restrict__ wWih_f, const float* __restrict__ wWih_b,
                                 const float* __restrict__ wWhh_f, const float* __restrict__ wWhh_b,
                                 const float* __restrict__ W1)
{
    int tid = blockIdx.x*blockDim.x + threadIdx.x;
    if (tid < 60000) {                              // word Wih packed: 2 x 75 x 400
        int which = tid / 30000;
        int rem = tid % 30000;
        int kp = rem / 400, g = rem % 400;
        const float* W = which ? wWih_b : wWih_f;
        (which ? d_WihP_b : d_WihP_f)[kp*400+g] = make_float2(W[g*150+2*kp], W[g*150+2*kp+1]);
        return;
    }
    int t2 = tid - 60000;
    if (t2 < 10000) {                               // W1 packed: 100 x 100
        int kp = t2 / 100, g = t2 % 100;
        d_W1P[kp*100+g] = make_float2(W1[g*200+2*kp], W1[g*200+2*kp+1]);
        return;
    }
    int t5 = t2 - 10000;
    if (t5 < 40000) {                               // word Whh packed: 2 x 50 x 400
        int which = t5 / 20000;
        int rem = t5 % 20000;
        int kp = rem / 400, g = rem % 400;
        const float* W = which ? wWhh_b : wWhh_f;
        (which ? d_wWhhP_b : d_wWhhP_f)[kp*400+g] = make_float2(W[g*100+2*kp], W[g*100+2*kp+1]);
    }
}

// ---------------- K1: char BiLSTM, one warp per (sequence, direction) ---------
__global__ void __launch_bounds__(256,2) char_lstm_kernel(
    const int* __restrict__ char_ids, const int* __restrict__ word_num)
{
    int warp = threadIdx.x >> 5;
    int lane = threadIdx.x & 31;
    int task = blockIdx.x*8 + warp;          // < 65536
    int seq = task >> 1;
    int dir = task & 1;

    // early-exit for masked sequences: char_out must be zero
    if ((seq & 255) >= word_num[seq >> 8]) {
        if (lane < 25) g_char_out[seq*50 + dir*25 + lane] = 0.f;
        return;
    }

    const float2* WhhP = dir ? d_cWhhP_b : d_cWhhP_f;
    const float*  W24  = dir ? d_cW24_b  : d_cW24_f;
    const float*  Etab = dir ? d_Eb : d_Ef;
    int l = (lane < 25) ? lane : 0;

    u64 wp[4][12]; float w24[4];
    #pragma unroll
    for (int j = 0; j < 4; j++) {
        #pragma unroll
        for (int kp = 0; kp < 12; kp++)
            wp[j][kp] = *(const u64*)&WhhP[kp*100 + 25*j + l];
        w24[j] = __ldg(&W24[25*j + l]);
    }

    __shared__ __align__(16) float sh[8][32];
    sh[warp][lane] = 0.f;
    __syncwarp();

    int idreg = (lane < 16) ? char_ids[seq*16 + lane] : 0;
    float c = 0.f, h = 0.f;

    #pragma unroll 1
    for (int t = 0; t < 16; t++) {
        int ct = dir ? (15 - t) : t;
        int row = __shfl_sync(0xffffffffu, idreg, ct);
        const float* e = Etab + row*100;
        u64 acc[4];
        acc[0] = pk2(__ldg(&e[l]),    0.f);
        acc[1] = pk2(__ldg(&e[25+l]), 0.f);
        acc[2] = pk2(__ldg(&e[50+l]), 0.f);
        acc[3] = pk2(__ldg(&e[75+l]), 0.f);
        const ulonglong2* h2 = (const ulonglong2*)sh[warp];
        #pragma unroll
        for (int k4 = 0; k4 < 6; k4++) {
            ulonglong2 v = h2[k4];
            #pragma unroll
            for (int j = 0; j < 4; j++) {
                acc[j] = fma2(wp[j][2*k4],   v.x, acc[j]);
                acc[j] = fma2(wp[j][2*k4+1], v.y, acc[j]);
            }
        }
        float h24 = sh[warp][24];
        float a[4];
        #pragma unroll
        for (int j = 0; j < 4; j++) {
            float lo, hi; upk2(lo, hi, acc[j]);
            a[j] = lo + hi + w24[j]*h24;
        }
        __syncwarp();
        float i_ = sigfast(a[0]);
        float f_ = sigfast(a[1]);
        float gg = tanhfast(a[2]);
        float o_ = sigfast(a[3]);
        c = f_*c + i_*gg;
        h = o_*tanhfast(c);
        if (lane < 25) sh[warp][lane] = h;
        __syncwarp();
    }
    if (lane < 25) {
        g_char_out[seq*50 + dir*25 + lane] = h;   // unmasked path: mask = 1
    }
}

// ---------------- K2: word input projection (R13 tile + masked-fwd skip) ------
// 32 rows x 100 gates x 1 dir per block, 256 threads; thread = 4 gates x 4 rows.
__global__ void __launch_bounds__(256) word_proj_kernel(
    const float* __restrict__ word_emb, const int* __restrict__ word_ids,
    const float* __restrict__ wb_f, const float* __restrict__ wb_b,
    const int* __restrict__ word_num)
{
    int rowbase = blockIdx.x * 32;
    int gbase = blockIdx.y * 100;
    int dir = blockIdx.z;
    // forward-dir masked-tile skip: gpre_f stays 0 there; only masked
    // (never-consumed) outputs depend on it.
    if (dir == 0 && (rowbase & 255) >= word_num[rowbase >> 8]) return;

    int tx = threadIdx.x & 31;
    int ty = threadIdx.x >> 5;   // 0..7

    __shared__ __align__(16) float sA[32*152];
    __shared__ int swid[32];

    if (threadIdx.x < 32) swid[threadIdx.x] = word_ids[rowbase + threadIdx.x];
    __syncthreads();
    for (int idx = threadIdx.x; idx < 32*150; idx += 256) {
        int r = idx / 150, k = idx % 150;
        float v;
        if (k < 100) v = __ldg(&word_emb[(size_t)swid[r]*100 + k]);
        else         v = g_char_out[(rowbase + r)*50 + (k - 100)];
        sA[r*152 + k] = v;
    }
    __syncthreads();

    const float2* WP  = dir ? d_WihP_b : d_WihP_f;
    const float* bias = dir ? wb_b : wb_f;
    int gidx[4]; bool gok[4];
    u64 acc[4][4];
    u64 z = pk2(0.f, 0.f);
    #pragma unroll
    for (int i = 0; i < 4; i++) {
        int lg = tx + 32*i;
        gok[i] = (lg < 100);
        gidx[i] = gbase + (gok[i] ? lg : 0);
        #pragma unroll
        for (int j = 0; j < 4; j++) acc[i][j] = z;
    }
    #pragma unroll 3
    for (int kp = 0; kp < 75; kp++) {
        u64 w[4];
        #pragma unroll
        for (int i = 0; i < 4; i++) w[i] = *(const u64*)&WP[kp*400 + gidx[i]];
        u64 a[4];
        #pragma unroll
        for (int j = 0; j < 4; j++) a[j] = *(const u64*)&sA[(ty + 8*j)*152 + 2*kp];
        #pragma unroll
        for (int i = 0; i < 4; i++) {
            #pragma unroll
            for (int j = 0; j < 4; j++) acc[i][j] = fma2(w[i], a[j], acc[i][j]);
        }
    }
    float* out = dir ? g_gpre_b : g_gpre_f;
    #pragma unroll
    for (int i = 0; i < 4; i++) {
        if (!gok[i]) continue;
        float bv = __ldg(&bias[gidx[i]]);
        #pragma unroll
        for (int j = 0; j < 4; j++) {
            size_t row = (size_t)(rowbase + ty + 8*j);
            float lo, hi;
            upk2(lo, hi, acc[i][j]);
            // pair-interleaved: ((row/2)*400 + g)*2 + (row&1)
            out[((row >> 1)*400 + gidx[i])*2 + (row & 1)] = bv + lo + hi;
        }
    }
}

// ---------------- K3: word BiLSTM recurrence (pair-interleaved gpre loads) ----
__global__ void __launch_bounds__(400,1) word_rec_kernel()
{
    int dir  = blockIdx.x & 1;
    int pair = blockIdx.x >> 1;
    int b0 = pair*2, b1 = b0 + 1;
    int g = threadIdx.x;                 // 0..399, all workers
    const float2* WhhP = dir ? d_wWhhP_b : d_wWhhP_f;

    u64 wp[50];
    #pragma unroll
    for (int kp = 0; kp < 50; kp++)
        wp[kp] = *(const u64*)&WhhP[kp*400 + g];

    __shared__ __align__(16) float sh0[100], sh1[100];
    __shared__ float sg0[400], sg1[400];
    if (g < 100) { sh0[g] = 0.f; sh1[g] = 0.f; }
    float c = 0.f;
    __syncthreads();

    const u64* gp0 = ((const u64*)(dir ? g_gpre_b : g_gpre_f)) + (size_t)b0*128*400;
    const u64* gp1 = ((const u64*)(dir ? g_gpre_b : g_gpre_f)) + (size_t)b1*128*400;

    int pfirst = dir ? 127 : 0;
    u64 pf0 = gp0[pfirst*400 + g];
    u64 pf1 = gp1[pfirst*400 + g];
    // branch-free nonlinearity: y = na*tanhfast(ns*x) + nb
    bool isg = (g >= 200 && g < 300);
    float ns = isg ? 1.0f : 0.5f;
    float na = ns;
    float nb = isg ? 0.0f : 0.5f;

    #pragma unroll 1
    for (int pp = 0; pp < 128; pp++) {
        int p = dir ? (127 - pp) : pp;
        u64 cp0 = pf0, cp1 = pf1;
        if (pp < 127) {
            int pn = dir ? (126 - pp) : (pp + 1);
            pf0 = gp0[pn*400 + g];
            pf1 = gp1[pn*400 + g];
        }
        float ev0, od0, ev1, od1;
        upk2(ev0, od0, cp0);
        upk2(ev1, od1, cp1);
        #pragma unroll
        for (int sub = 0; sub < 2; sub++) {
            int ts = 2*p + (dir ? (1 - sub) : sub);
            float cur0 = (ts & 1) ? od0 : ev0;
            float cur1 = (ts & 1) ? od1 : ev1;
            {
                u64 a0x = pk2(cur0, 0.f), a0y = pk2(0.f, 0.f);
                u64 a1x = pk2(cur1, 0.f), a1y = pk2(0.f, 0.f);
                const ulonglong2* h20 = (const ulonglong2*)sh0;
                const ulonglong2* h21 = (const ulonglong2*)sh1;
                #pragma unroll
                for (int k4 = 0; k4 < 25; k4++) {
                    ulonglong2 v0 = h20[k4];
                    ulonglong2 v1 = h21[k4];
                    a0x = fma2(wp[2*k4],   v0.x, a0x);
                    a0y = fma2(wp[2*k4+1], v0.y, a0y);
                    a1x = fma2(wp[2*k4],   v1.x, a1x);
                    a1y = fma2(wp[2*k4+1], v1.y, a1y);
                }
                float l0,h0v,l1,h1v,l2,h2v,l3,h3v;
                upk2(l0,h0v,a0x); upk2(l1,h1v,a0y);
                upk2(l2,h2v,a1x); upk2(l3,h3v,a1y);
                float x0 = (l0+h0v) + (l1+h1v);
                float x1 = (l2+h2v) + (l3+h3v);
                sg0[g] = fmaf(na, tanhfast(ns*x0), nb);
                sg1[g] = fmaf(na, tanhfast(ns*x1), nb);
            }
            __syncthreads();
            if (g < 200) {
                int s = (g >= 100); int j = g - s*100;
                const float* sg = s ? sg1 : sg0;
                float i_ = sg[j];
                float f_ = sg[100+j];
                float gt = sg[200+j];
                float o_ = sg[300+j];
                c = f_*c + i_*gt;
                float h = o_*tanhfast(c);
                (s ? sh1 : sh0)[j] = h;
                g_wh[((size_t)((b0+s)*256 + ts))*200 + dir*100 + j] = h;
            }
            __syncthreads();
        }
    }
}

// ---------------- K4: MLP (pair-packed W1, masked-group early exit) -----------
__global__ void __launch_bounds__(128) mlp_kernel(
    const float* __restrict__ b1, const float* __restrict__ W2,
    const float* __restrict__ b2, const int* __restrict__ word_num)
{
    int rowbase = blockIdx.x * 16;
    int wn = word_num[rowbase >> 8];
    if ((rowbase & 255) >= wn) return;   // whole 16-row group masked -> unused

    __shared__ __align__(16) float sX[16*200];
    __shared__ float sH[16*104];
    int tid = threadIdx.x;

    for (int idx = tid; idx < 3200; idx += 128)
        sX[idx] = g_wh[(size_t)rowbase*200 + idx];
    __syncthreads();
    if (tid < 100) {
        u64 a2[16];
        u64 z = pk2(0.f, 0.f);
        #pragma unroll
        for (int r = 0; r < 16; r++) a2[r] = z;
        #pragma unroll 2
        for (int kp = 0; kp < 100; kp++) {
            u64 wv = *(const u64*)&d_W1P[kp*100 + tid];
            #pragma unroll
            for (int r = 0; r < 16; r++)
                a2[r] = fma2(wv, *(const u64*)&sX[r*200 + 2*kp], a2[r]);
        }
        float bv = __ldg(&b1[tid]);
        #pragma unroll
        for (int r = 0; r < 16; r++) {
            float lo, hi; upk2(lo, hi, a2[r]);
            sH[r*104 + tid] = tanhfast(bv + lo + hi);
        }
    }
    __syncthreads();
    #pragma unroll
    for (int pass = 0; pass < 2; pass++) {
        int idx = tid + pass*128;
        if (idx < 144) {
            int r = idx / 9, o = idx % 9;
            int row = rowbase + r;
            float acc = __ldg(&b2[o]);
            #pragma unroll 4
            for (int k = 0; k < 100; k++)
                acc += __ldg(&W2[o*100 + k]) * sH[r*104 + k];
            float m = ((row & 255) < wn) ? 1.0f : 0.0f;
            g_feats[row*9 + o] = acc * m;
        }
    }
}

// ---------------- K5: CRF (parallel numerator + forward algorithm) ------------
__global__ void crf_kernel(const float* __restrict__ transition,
                           const int* __restrict__ word_num,
                           const int* __restrict__ label_ids)
{
    int b = blockIdx.x;
    int lane = threadIdx.x;
    __shared__ float sT[121];
    __shared__ int sLab[256];
    for (int i = lane; i < 121; i += 32) sT[i] = transition[i];
    #pragma unroll
    for (int r = 0; r < 8; r++) sLab[lane + 32*r] = label_ids[b*256 + lane + 32*r];
    __syncwarp();
    int wn = word_num[b];

    // --- numerator: lane-parallel gold-path score ---
    float part = 0.f;
    #pragma unroll
    for (int r = 0; r < 8; r++) {
        int t = lane + 32*r;
        if (t < wn) {
            int lab = sLab[t];
            int prv = (t == 0) ? 9 : sLab[t-1];
            part += g_feats[(size_t)(b*256 + t)*9 + lab] + sT[prv*11 + lab];
        }
    }
    #pragma unroll
    for (int off = 16; off > 0; off >>= 1)
        part += __shfl_xor_sync(0xffffffffu, part, off);
    float num = part + sT[sLab[wn-1]*11 + 10];

    // --- denominator: forward algorithm ---
    float alpha = (lane == 9) ? 0.0f : SMALLV;   // start state = 9
    int jj = (lane < 11) ? lane : 0;
    for (int t = 0; t < wn; t++) {
        float obs = (lane < 9) ? g_feats[(size_t)(b*256 + t)*9 + lane] : SMALLV;
        float av[11];
        #pragma unroll
        for (int k = 0; k < 11; k++) av[k] = __shfl_sync(0xffffffffu, alpha, k);
        float mx = -3.0e38f;
        float vv[11];
        #pragma unroll
        for (int k = 0; k < 11; k++) { vv[k] = av[k] + sT[k*11 + jj]; mx = fmaxf(mx, vv[k]); }
        float s = 0.f;
        #pragma unroll
        for (int k = 0; k < 11; k++) s += expf(vv[k] - mx);
        float anew = obs + mx + logf(s);
        alpha = (lane < 11) ? anew : SMALLV;
    }
    float av[11];
    #pragma unroll
    for (int k = 0; k < 11; k++) av[k] = __shfl_sync(0xffffffffu, alpha, k);
    if (lane == 0) {
        float mx = -3.0e38f; float vv[11];
        #pragma unroll
        for (int k = 0; k < 11; k++) { vv[k] = av[k] + sT[k*11 + 10]; mx = fmaxf(mx, vv[k]); }
        float s = 0.f;
        #pragma unroll
        for (int k = 0; k < 11; k++) s += expf(vv[k] - mx);
        float denom = mx + logf(s);
        g_perb[b] = denom - num;
    }
}

// ---------------- K6: deterministic mean reduction ----------------------------
__global__ void finalize_kernel(float* out)
{
    __shared__ float s[128];
    int tid = threadIdx.x;
    s[tid] = g_perb[tid];
    __syncthreads();
    for (int off = 64; off > 0; off >>= 1) {
        if (tid < off) s[tid] += s[tid + off];
        __syncthreads();
    }
    if (tid == 0) out[0] = s[0] * (1.0f/128.0f);
}

// ---------------- launch -------------------------------------------------------
extern "C" void kernel_launch(void* const* d_in, const int* in_sizes, int n_in,
                              void* d_out, int out_size)
{
    (void)in_sizes; (void)n_in; (void)out_size;
    const float* word_emb   = (const float*)d_in[0];
    const float* char_emb   = (const float*)d_in[1];
    const float* cWih_f     = (const float*)d_in[2];
    const float* cWhh_f     = (const float*)d_in[3];
    const float* cb_f       = (const float*)d_in[4];
    const float* cWih_b     = (const float*)d_in[5];
    const float* cWhh_b     = (const float*)d_in[6];
    const float* cb_b       = (const float*)d_in[7];
    const float* wWih_f     = (const float*)d_in[8];
    const float* wWhh_f     = (const float*)d_in[9];
    const float* wb_f       = (const float*)d_in[10];
    const float* wWih_b     = (const float*)d_in[11];
    const float* wWhh_b     = (const float*)d_in[12];
    const float* wb_b       = (const float*)d_in[13];
    const float* W1         = (const float*)d_in[14];
    const float* b1         = (const float*)d_in[15];
    const float* W2         = (const float*)d_in[16];
    const float* b2         = (const float*)d_in[17];
    const float* transition = (const float*)d_in[18];
    const int*   word_num   = (const int*)d_in[19];
    const int*   word_ids   = (const int*)d_in[20];
    const int*   char_ids   = (const int*)d_in[21];
    const int*   label_ids  = (const int*)d_in[22];

    static cudaStream_t s2 = 0;
    static cudaEvent_t evFork = 0, evJoin = 0;
    if (s2 == 0) {
        cudaStreamCreateWithFlags(&s2, cudaStreamNonBlocking);
        cudaEventCreateWithFlags(&evFork, cudaEventDisableTiming);
        cudaEventCreateWithFlags(&evJoin, cudaEventDisableTiming);
    }

    prep_char_kernel<<<89, 256>>>(char_emb, cWih_f, cb_f, cWih_b, cb_b, cWhh_f, cWhh_b);

    // prep_word runs concurrently with char_lstm (no data dependence)
    cudaEventRecord(evFork, 0);
    cudaStreamWaitEvent(s2, evFork, 0);
    prep_word_kernel<<<430, 256, 0, s2>>>(wWih_f, wWih_b, wWhh_f, wWhh_b, W1);

    char_lstm_kernel<<<8192, 256>>>(char_ids, word_num);

    // join: word_proj needs both char_out (stream 0) and packed Wih (s2)
    cudaEventRecord(evJoin, s2);
    cudaStreamWaitEvent(0, evJoin, 0);

    dim3 g2(1024, 4, 2);
    word_proj_kernel<<<g2, 256>>>(word_emb, word_ids, wb_f, wb_b, word_num);
    word_rec_kernel<<<128, 400>>>();
    mlp_kernel<<<2048, 128>>>(b1, W2, b2, word_num);
    crf_kernel<<<128, 32>>>(transition, word_num, label_ids);
    finalize_kernel<<<1, 128>>>((float*)d_out);
}